// round 2
// baseline (speedup 1.0000x reference)
#include <cuda_runtime.h>
#include <cstdint>

// Problem constants
#define BATCH 4
#define CCH   256      // channels
#define HWPX  4096     // 64*64
#define MID   64

// ---------------- scratch (device globals: allocation-free rule) -------------
__device__ float g_T[BATCH * MID * HWPX];                    //  4 MB
__device__ float g_K[BATCH * CCH * HWPX];                    // 16 MB
__device__ float g_Q[BATCH * CCH * HWPX];                    // 16 MB
__device__ float g_V[BATCH * CCH * HWPX];                    // 16 MB
__device__ float g_P[(size_t)BATCH * HWPX * HWPX];           // 256 MB  P = exp(Et)
__device__ float g_Zpart[BATCH * 64 * HWPX];                 //  4 MB  partial row sums
__device__ float g_Zinv[BATCH * HWPX];                       // 64 KB

// ---------------------------------------------------------------------------
// 1) T[b,m,p] = relu( (w1[m]*inv[m]) * bm[b,p] + (bias[m]-mean[m]*inv[m]) )
//    bm = nearest-downsampled boundary map (src idx = 2*dst idx)
// ---------------------------------------------------------------------------
__global__ void key_mid_kernel(const float* __restrict__ bmap,
                               const float* __restrict__ w1,
                               const float* __restrict__ bnscale,
                               const float* __restrict__ bnbias,
                               const float* __restrict__ bnmean,
                               const float* __restrict__ bnvar)
{
    int idx = blockIdx.x * 256 + threadIdx.x;       // over BATCH*MID*HWPX
    int p = idx & (HWPX - 1);
    int m = (idx >> 12) & (MID - 1);
    int b = idx >> 18;
    float inv = bnscale[m] * rsqrtf(bnvar[m] + 1e-5f);
    float a   = w1[m] * inv;
    float bb  = bnbias[m] - bnmean[m] * inv;
    int y = p >> 6, x = p & 63;
    float s = bmap[b * 16384 + y * 256 + x * 2];    // boundary[b,0,2y,2x]
    g_T[idx] = fmaxf(fmaf(a, s, bb), 0.0f);
}

// ---------------------------------------------------------------------------
// 2) Shared-weight SGEMM: C[b] (256 x 4096) = W (256 x KD) * B[b] (KD x 4096)
//    mode 0: W=key_w2  (KD=64),  B=g_T, C=g_K
//    mode 1: W=query_w (KD=256), B=U,   C=g_Q
//    mode 2: W=value_w (KD=256), B=U,   C=g_V
// Tiling: BM=BN=64, BK=16, 256 threads, 4x4 microtile.
// ---------------------------------------------------------------------------
__global__ void __launch_bounds__(256) sgemm_w_kernel(const float* __restrict__ W,
                                                      const float* __restrict__ Uin,
                                                      int mode)
{
    const int N = HWPX;
    const int KD = (mode == 0) ? MID : CCH;
    int b = blockIdx.z;
    const float* Bp = ((mode == 0) ? g_T : Uin) + (size_t)b * KD * N;
    float* Cp = ((mode == 0) ? g_K : (mode == 1 ? g_Q : g_V)) + (size_t)b * CCH * N;

    int m0 = blockIdx.y * 64, n0 = blockIdx.x * 64;
    __shared__ float As[16][64];
    __shared__ float Bs[16][64];
    int tid = threadIdx.x;
    int tx = tid & 15, ty = tid >> 4;
    float acc[4][4] = {};

    for (int k0 = 0; k0 < KD; k0 += 16) {
        {   // A tile: rows m0..m0+63, cols k0..k0+15 (transposed into As[k][m])
            int row = tid >> 2, q = tid & 3;
            float4 a4 = *(const float4*)(W + (size_t)(m0 + row) * KD + k0 + q * 4);
            As[q * 4 + 0][row] = a4.x; As[q * 4 + 1][row] = a4.y;
            As[q * 4 + 2][row] = a4.z; As[q * 4 + 3][row] = a4.w;
        }
        {   // B tile: rows k0..k0+15, cols n0..n0+63
            int kk = tid >> 4, nn = (tid & 15) * 4;
            *(float4*)&Bs[kk][nn] = *(const float4*)(Bp + (size_t)(k0 + kk) * N + n0 + nn);
        }
        __syncthreads();
#pragma unroll
        for (int kk = 0; kk < 16; ++kk) {
            float4 av = *(const float4*)&As[kk][ty << 2];
            float4 bv = *(const float4*)&Bs[kk][tx << 2];
            float ar[4] = {av.x, av.y, av.z, av.w};
            float br[4] = {bv.x, bv.y, bv.z, bv.w};
#pragma unroll
            for (int r = 0; r < 4; ++r)
#pragma unroll
                for (int s = 0; s < 4; ++s)
                    acc[r][s] = fmaf(ar[r], br[s], acc[r][s]);
        }
        __syncthreads();
    }
#pragma unroll
    for (int r = 0; r < 4; ++r) {
        float4 o4 = make_float4(acc[r][0], acc[r][1], acc[r][2], acc[r][3]);
        *(float4*)(Cp + (size_t)(m0 + ty * 4 + r) * N + n0 + tx * 4) = o4;
    }
}

// ---------------------------------------------------------------------------
// 3) P[b,i,j] = exp( sum_c K[b,c,i] * Q[b,c,j] )   (energy transposed)
//    Also emits per-(row i, j-tile) partial sums into g_Zpart (deterministic).
// ---------------------------------------------------------------------------
__global__ void __launch_bounds__(256) energy_exp_kernel()
{
    const int N = HWPX, KD = CCH;
    int b = blockIdx.z;
    const float* Ap = g_K + (size_t)b * KD * N;   // A[i,c] = Ap[c*N + i]
    const float* Bp = g_Q + (size_t)b * KD * N;   // B[c,j]
    float* Pp = g_P + (size_t)b * N * N;

    int i0 = blockIdx.y * 64, j0 = blockIdx.x * 64;
    __shared__ float As[16][64];
    __shared__ float Bs[16][64];
    int tid = threadIdx.x;
    int tx = tid & 15, ty = tid >> 4;
    float acc[4][4] = {};

    for (int c0 = 0; c0 < KD; c0 += 16) {
        {   // A (already k-major in memory along i): coalesced float4 along i
            int cc = tid >> 4, ii = (tid & 15) * 4;
            *(float4*)&As[cc][ii] = *(const float4*)(Ap + (size_t)(c0 + cc) * N + i0 + ii);
        }
        {
            int kk = tid >> 4, nn = (tid & 15) * 4;
            *(float4*)&Bs[kk][nn] = *(const float4*)(Bp + (size_t)(c0 + kk) * N + j0 + nn);
        }
        __syncthreads();
#pragma unroll
        for (int kk = 0; kk < 16; ++kk) {
            float4 av = *(const float4*)&As[kk][ty << 2];
            float4 bv = *(const float4*)&Bs[kk][tx << 2];
            float ar[4] = {av.x, av.y, av.z, av.w};
            float br[4] = {bv.x, bv.y, bv.z, bv.w};
#pragma unroll
            for (int r = 0; r < 4; ++r)
#pragma unroll
                for (int s = 0; s < 4; ++s)
                    acc[r][s] = fmaf(ar[r], br[s], acc[r][s]);
        }
        __syncthreads();
    }

    float rs[4];
#pragma unroll
    for (int r = 0; r < 4; ++r) {
        float4 p;
        p.x = __expf(acc[r][0]); p.y = __expf(acc[r][1]);
        p.z = __expf(acc[r][2]); p.w = __expf(acc[r][3]);
        rs[r] = (p.x + p.y) + (p.z + p.w);
        *(float4*)(Pp + (size_t)(i0 + ty * 4 + r) * N + j0 + tx * 4) = p;
    }
    // reduce rs across the 16 tx lanes (fixed order -> deterministic)
#pragma unroll
    for (int off = 8; off > 0; off >>= 1) {
#pragma unroll
        for (int r = 0; r < 4; ++r)
            rs[r] += __shfl_xor_sync(0xffffffffu, rs[r], off);
    }
    if (tx == 0) {
#pragma unroll
        for (int r = 0; r < 4; ++r)
            g_Zpart[(size_t)(b * 64 + blockIdx.x) * HWPX + i0 + ty * 4 + r] = rs[r];
    }
}

// ---------------------------------------------------------------------------
// 4) Zinv[b,i] = 1 / sum_jt Zpart[b,jt,i]   (fixed order, coalesced)
// ---------------------------------------------------------------------------
__global__ void zinv_kernel()
{
    int t = blockIdx.x * 256 + threadIdx.x;   // 0 .. BATCH*HWPX-1
    int b = t >> 12;
    int i = t & (HWPX - 1);
    float s = 0.0f;
#pragma unroll
    for (int jt = 0; jt < 64; ++jt)
        s += g_Zpart[(size_t)(b * 64 + jt) * HWPX + i];
    g_Zinv[t] = 1.0f / s;
}

// ---------------------------------------------------------------------------
// 5) Out[b,c,j] = gamma * ( sum_i (V[b,c,i]*Zinv[b,i]) * P[b,i,j] ) + U[b,c,j]
// ---------------------------------------------------------------------------
__global__ void __launch_bounds__(256) out_kernel(const float* __restrict__ Uin,
                                                  const float* __restrict__ gammap,
                                                  float* __restrict__ Out)
{
    const int N = HWPX, KD = HWPX;
    int b = blockIdx.z;
    const float* Ap = g_V + (size_t)b * CCH * KD;
    const float* Bp = g_P + (size_t)b * (size_t)KD * N;
    const float* zi = g_Zinv + (size_t)b * KD;
    const float* Up = Uin + (size_t)b * CCH * N;
    float* Cp = Out + (size_t)b * CCH * N;
    float gamma = __ldg(gammap);

    int m0 = blockIdx.y * 64, n0 = blockIdx.x * 64;
    __shared__ float As[16][64];
    __shared__ float Bs[16][64];
    int tid = threadIdx.x;
    int tx = tid & 15, ty = tid >> 4;
    float acc[4][4] = {};

    for (int k0 = 0; k0 < KD; k0 += 16) {
        {   // A tile with per-k 1/Z scaling folded into the load
            int row = tid >> 2, q = tid & 3;
            float4 a4 = *(const float4*)(Ap + (size_t)(m0 + row) * KD + k0 + q * 4);
            float4 z4 = *(const float4*)(zi + k0 + q * 4);
            a4.x *= z4.x; a4.y *= z4.y; a4.z *= z4.z; a4.w *= z4.w;
            As[q * 4 + 0][row] = a4.x; As[q * 4 + 1][row] = a4.y;
            As[q * 4 + 2][row] = a4.z; As[q * 4 + 3][row] = a4.w;
        }
        {
            int kk = tid >> 4, nn = (tid & 15) * 4;
            *(float4*)&Bs[kk][nn] = *(const float4*)(Bp + (size_t)(k0 + kk) * N + n0 + nn);
        }
        __syncthreads();
#pragma unroll
        for (int kk = 0; kk < 16; ++kk) {
            float4 av = *(const float4*)&As[kk][ty << 2];
            float4 bv = *(const float4*)&Bs[kk][tx << 2];
            float ar[4] = {av.x, av.y, av.z, av.w};
            float br[4] = {bv.x, bv.y, bv.z, bv.w};
#pragma unroll
            for (int r = 0; r < 4; ++r)
#pragma unroll
                for (int s = 0; s < 4; ++s)
                    acc[r][s] = fmaf(ar[r], br[s], acc[r][s]);
        }
        __syncthreads();
    }
#pragma unroll
    for (int r = 0; r < 4; ++r) {
        size_t off = (size_t)(m0 + ty * 4 + r) * N + n0 + tx * 4;
        float4 u4 = *(const float4*)(Up + off);
        float4 o4;
        o4.x = fmaf(gamma, acc[r][0], u4.x);
        o4.y = fmaf(gamma, acc[r][1], u4.y);
        o4.z = fmaf(gamma, acc[r][2], u4.z);
        o4.w = fmaf(gamma, acc[r][3], u4.w);
        *(float4*)(Cp + off) = o4;
    }
}

// ---------------------------------------------------------------------------
extern "C" void kernel_launch(void* const* d_in, const int* in_sizes, int n_in,
                              void* d_out, int out_size)
{
    const float* bmap     = (const float*)d_in[0];
    const float* U        = (const float*)d_in[1];
    const float* key_w1   = (const float*)d_in[2];
    const float* bn_scale = (const float*)d_in[3];
    const float* bn_bias  = (const float*)d_in[4];
    const float* bn_mean  = (const float*)d_in[5];
    const float* bn_var   = (const float*)d_in[6];
    const float* key_w2   = (const float*)d_in[7];
    const float* query_w  = (const float*)d_in[8];
    const float* value_w  = (const float*)d_in[9];
    const float* gamma    = (const float*)d_in[10];
    float* out = (float*)d_out;

    // 1) mid activations for the key path
    key_mid_kernel<<<(BATCH * MID * HWPX) / 256, 256>>>(bmap, key_w1, bn_scale,
                                                        bn_bias, bn_mean, bn_var);
    // 2) K = key_w2 @ T ; Q = query_w @ U ; V = value_w @ U
    sgemm_w_kernel<<<dim3(64, 4, BATCH), 256>>>(key_w2,  nullptr, 0);
    sgemm_w_kernel<<<dim3(64, 4, BATCH), 256>>>(query_w, U,       1);
    sgemm_w_kernel<<<dim3(64, 4, BATCH), 256>>>(value_w, U,       2);
    // 3) P = exp(K^T Q) + partial row sums
    energy_exp_kernel<<<dim3(64, 64, BATCH), 256>>>();
    // 4) Zinv
    zinv_kernel<<<(BATCH * HWPX) / 256, 256>>>();
    // 5) final output
    out_kernel<<<dim3(64, 4, BATCH), 256>>>(U, gamma, out);
}

// round 5
// speedup vs baseline: 7.4044x; 7.4044x over previous
#include <cuda_runtime.h>
#include <cuda_bf16.h>
#include <cstdint>

#define BATCH 4
#define CCH   256
#define HW    4096
#define MID   64

using bf16 = __nv_bfloat16;

// ---------------- device-global scratch (allocation-free rule) --------------
__device__ __align__(1024) bf16 g_Ut[(size_t)BATCH * HW * CCH];   // [b][j][c]   8MB
__device__ __align__(1024) bf16 g_Tt[(size_t)BATCH * HW * MID];   // [b][p][m]   2MB
__device__ __align__(1024) bf16 g_Wq[CCH * CCH];
__device__ __align__(1024) bf16 g_Wv[CCH * CCH];
__device__ __align__(1024) bf16 g_Wk[CCH * MID];
__device__ __align__(1024) bf16 g_Qt[(size_t)BATCH * HW * CCH];   // [b][j][c]
__device__ __align__(1024) bf16 g_Kt[(size_t)BATCH * HW * CCH];   // [b][i][c]
__device__ __align__(1024) bf16 g_Vz[(size_t)BATCH * CCH * HW];   // [b][c][i]
__device__ __align__(1024) bf16 g_S [(size_t)BATCH * HW * HW];    // [b][j][i] 128MB
__device__ float g_Zp[(size_t)BATCH * 256 * HW];                  // 16MB partials
__device__ float g_Zi[BATCH * HW];

// ---------------- PTX helpers ----------------------------------------------
__device__ __forceinline__ uint32_t smem_u32(const void* p) {
    uint32_t a;
    asm("{ .reg .u64 t; cvta.to.shared.u64 t, %1; cvt.u32.u64 %0, t; }"
        : "=r"(a) : "l"(p));
    return a;
}
__device__ __forceinline__ void cp16(uint32_t s, const void* g) {
    asm volatile("cp.async.cg.shared.global [%0], [%1], 16;" :: "r"(s), "l"(g));
}
#define CP_COMMIT() asm volatile("cp.async.commit_group;" ::: "memory")
#define CP_WAIT(n)  asm volatile("cp.async.wait_group %0;" :: "n"(n) : "memory")

__device__ __forceinline__ void ldsm4(uint32_t* r, uint32_t a) {
    asm volatile("ldmatrix.sync.aligned.m8n8.x4.shared.b16 {%0,%1,%2,%3}, [%4];"
                 : "=r"(r[0]), "=r"(r[1]), "=r"(r[2]), "=r"(r[3]) : "r"(a));
}
__device__ __forceinline__ void mma_bf16(float* d, const uint32_t* a,
                                         uint32_t b0, uint32_t b1) {
    asm volatile("mma.sync.aligned.m16n8k16.row.col.f32.bf16.bf16.f32 "
                 "{%0,%1,%2,%3}, {%4,%5,%6,%7}, {%8,%9}, {%0,%1,%2,%3};"
                 : "+f"(d[0]), "+f"(d[1]), "+f"(d[2]), "+f"(d[3])
                 : "r"(a[0]), "r"(a[1]), "r"(a[2]), "r"(a[3]), "r"(b0), "r"(b1));
}

// SMEM: 3 stages x (A 16KB + B 16KB) = 96KB; epilogue staging reuses it.
#define STAGE_BYTES 32768
#define SMEM_BYTES  (3 * STAGE_BYTES + 128)
#define EPI_STRIDE  136   // elems; 136*4B=544B -> +4 banks/row: conflict-free

// load one 128x64-bf16 tile (128B rows) K-chunk, SW128 swizzle
__device__ __forceinline__ void ldtile(uint32_t sbuf, const char* g,
                                       size_t stride, int tid) {
#pragma unroll
    for (int u = 0; u < 4; ++u) {
        int idx = tid + u * 256;            // 1024 chunks of 16B
        int r = idx >> 3, s = idx & 7;
        cp16(sbuf + r * 128 + (((s ^ (r & 7))) << 4), g + (size_t)r * stride + (s << 4));
    }
}

// ---------------------------------------------------------------------------
// HMMA GEMM: D[128 x 128] = A(128 rows, K) * B(128 rows, K)^T, all K-major bf16
// MODE 0: Qt  A=Ut(j)  B=Wq(c)  K=256 -> Qt[j][c]
// MODE 1: Kt  A=Tt(p)  B=Wk(c)  K=64  -> Kt[p][c]
// MODE 2: S   A=Qt(j)  B=Kt(i)  K=256 -> S[j][i]=exp(E), Zp partials
// MODE 3: Vz  A=Wv(c)  B=Ut(i)  K=256 -> Vz[c][i]*Zinv[i]
// MODE 4: Out A=Vz(c)  B=S(j)   K=4096-> out[c][j]=gamma*x+U[c][j]
// ---------------------------------------------------------------------------
template<int MODE>
__global__ void __launch_bounds__(256, 2) gemm_hmma(const float* __restrict__ U,
                                                    const float* __restrict__ gammap,
                                                    float* __restrict__ Out)
{
    extern __shared__ char smem_raw[];
    uint32_t sb = (smem_u32(smem_raw) + 127u) & ~127u;
    const int tid = threadIdx.x, lane = tid & 31, wid = tid >> 5;
    const int wm = wid & 1, wn = wid >> 1;          // 2 x 4 warp grid
    const int b = blockIdx.z;
    const int m0 = blockIdx.y * 128, n0 = blockIdx.x * 128;

    constexpr int K  = (MODE == 1) ? MID : (MODE == 4 ? HW : CCH);
    constexpr int NC = K / 64;

    const char *gA, *gB;
    size_t strA, strB;
    if (MODE == 0) {
        gA = (const char*)(g_Ut + ((size_t)b * HW + m0) * CCH); strA = CCH * 2;
        gB = (const char*)(g_Wq + (size_t)n0 * CCH);            strB = CCH * 2;
    } else if (MODE == 1) {
        gA = (const char*)(g_Tt + ((size_t)b * HW + m0) * MID); strA = MID * 2;
        gB = (const char*)(g_Wk + (size_t)n0 * MID);            strB = MID * 2;
    } else if (MODE == 2) {
        gA = (const char*)(g_Qt + ((size_t)b * HW + m0) * CCH); strA = CCH * 2;
        gB = (const char*)(g_Kt + ((size_t)b * HW + n0) * CCH); strB = CCH * 2;
    } else if (MODE == 3) {
        gA = (const char*)(g_Wv + (size_t)m0 * CCH);            strA = CCH * 2;
        gB = (const char*)(g_Ut + ((size_t)b * HW + n0) * CCH); strB = CCH * 2;
    } else {
        gA = (const char*)(g_Vz + (size_t)b * CCH * HW + (size_t)m0 * HW); strA = HW * 2;
        gB = (const char*)(g_S + (size_t)b * HW * HW + (size_t)n0 * HW);   strB = HW * 2;
    }

    float acc[4][4][4] = {};

    // prologue: stages 0,1
    ldtile(sb, gA, strA, tid);
    ldtile(sb + 16384, gB, strB, tid);
    CP_COMMIT();
    if (NC > 1) {
        ldtile(sb + STAGE_BYTES, gA + 128, strA, tid);
        ldtile(sb + STAGE_BYTES + 16384, gB + 128, strB, tid);
    }
    CP_COMMIT();

#pragma unroll 1
    for (int n = 0; n < NC; ++n) {
        CP_WAIT(1);
        __syncthreads();
        if (n + 2 < NC) {   // prefetch into slot (n+2)%3 (== slot of chunk n-1)
            uint32_t sp = sb + ((n + 2) % 3) * STAGE_BYTES;
            ldtile(sp, gA + (size_t)(n + 2) * 128, strA, tid);
            ldtile(sp + 16384, gB + (size_t)(n + 2) * 128, strB, tid);
        }
        CP_COMMIT();

        uint32_t sA = sb + (n % 3) * STAGE_BYTES;
        uint32_t sB = sA + 16384;
#pragma unroll
        for (int kt = 0; kt < 4; ++kt) {
            uint32_t af[4][4], bfr[2][4];
            int s16 = kt * 2 + (lane >> 4);
#pragma unroll
            for (int mt = 0; mt < 4; ++mt) {
                int row = wm * 64 + mt * 16 + (lane & 15);
                ldsm4(af[mt], sA + row * 128 + ((s16 ^ (row & 7)) << 4));
            }
#pragma unroll
            for (int g = 0; g < 2; ++g) {
                int row = wn * 32 + g * 16 + (lane & 15);
                ldsm4(bfr[g], sB + row * 128 + ((s16 ^ (row & 7)) << 4));
            }
#pragma unroll
            for (int mt = 0; mt < 4; ++mt)
#pragma unroll
                for (int nt = 0; nt < 4; ++nt)
                    mma_bf16(acc[mt][nt], af[mt],
                             bfr[nt >> 1][nt & 1], bfr[nt >> 1][(nt & 1) + 2]);
        }
    }
    CP_WAIT(0);
    __syncthreads();    // pipeline drained; smem free for epilogue staging

    // ---------------- epilogue: stage tile in smem, coalesced store ---------
    const int r0 = wm * 64 + (lane >> 2);
    const int c0base = wn * 32 + 2 * (lane & 3);

    if (MODE <= 2) {
        // bf16 staging (MODE2 applies exp first)
        bf16* st = (bf16*)(smem_raw + (sb - smem_u32(smem_raw)));
#pragma unroll
        for (int mt = 0; mt < 4; ++mt)
#pragma unroll
            for (int nt = 0; nt < 4; ++nt) {
                float v0 = acc[mt][nt][0], v1 = acc[mt][nt][1];
                float v2 = acc[mt][nt][2], v3 = acc[mt][nt][3];
                if (MODE == 2) {
                    v0 = __expf(v0); v1 = __expf(v1);
                    v2 = __expf(v2); v3 = __expf(v3);
                }
                int r = r0 + mt * 16, c = c0base + nt * 8;
                *(__nv_bfloat162*)&st[r * EPI_STRIDE + c] = __floats2bfloat162_rn(v0, v1);
                *(__nv_bfloat162*)&st[(r + 8) * EPI_STRIDE + c] = __floats2bfloat162_rn(v2, v3);
            }
        __syncthreads();

        if (MODE == 2) {
            bf16* Sp = g_S + (size_t)b * HW * HW;
            int ch = tid & 31, h = tid >> 5;           // h: 0..7 row-groups of 16
            float zs0 = 0, zs1 = 0, zs2 = 0, zs3 = 0;
#pragma unroll
            for (int r = 0; r < 16; ++r) {
                int row = h * 16 + r;
                uint2 v = *(uint2*)&st[row * EPI_STRIDE + ch * 4];
                __nv_bfloat162 lo = *reinterpret_cast<__nv_bfloat162*>(&v.x);
                __nv_bfloat162 hi = *reinterpret_cast<__nv_bfloat162*>(&v.y);
                zs0 += __bfloat162float(lo.x); zs1 += __bfloat162float(lo.y);
                zs2 += __bfloat162float(hi.x); zs3 += __bfloat162float(hi.y);
                *(uint2*)&Sp[(size_t)(m0 + row) * HW + n0 + ch * 4] = v;
            }
            float4 z4 = make_float4(zs0, zs1, zs2, zs3);
            *(float4*)&g_Zp[((size_t)b * 256 + blockIdx.y * 8 + h) * HW + n0 + ch * 4] = z4;
        } else {
            bf16* dst = (MODE == 0 ? g_Qt : g_Kt) + (size_t)b * HW * CCH;
#pragma unroll
            for (int u = 0; u < 16; ++u) {
                int idx = tid + u * 256;               // 128 rows x 32 chunks
                int row = idx >> 5, ch = idx & 31;
                uint2 v = *(uint2*)&st[row * EPI_STRIDE + ch * 4];
                *(uint2*)&dst[(size_t)(m0 + row) * CCH + n0 + ch * 4] = v;
            }
        }
    } else {
        // fp32 staging
        float* st = (float*)(smem_raw + (sb - smem_u32(smem_raw)));
#pragma unroll
        for (int mt = 0; mt < 4; ++mt)
#pragma unroll
            for (int nt = 0; nt < 4; ++nt) {
                int r = r0 + mt * 16, c = c0base + nt * 8;
                *(float2*)&st[r * EPI_STRIDE + c] = make_float2(acc[mt][nt][0], acc[mt][nt][1]);
                *(float2*)&st[(r + 8) * EPI_STRIDE + c] = make_float2(acc[mt][nt][2], acc[mt][nt][3]);
            }
        __syncthreads();

        if (MODE == 3) {
            bf16* Vp = g_Vz;
#pragma unroll
            for (int u = 0; u < 16; ++u) {
                int idx = tid + u * 256;
                int row = idx >> 5, ch = idx & 31;
                float4 v = *(float4*)&st[row * EPI_STRIDE + ch * 4];
                float4 z = *(const float4*)&g_Zi[b * HW + n0 + ch * 4];
                __nv_bfloat162 lo = __floats2bfloat162_rn(v.x * z.x, v.y * z.y);
                __nv_bfloat162 hi = __floats2bfloat162_rn(v.z * z.z, v.w * z.w);
                uint2 o; o.x = *reinterpret_cast<uint32_t*>(&lo);
                o.y = *reinterpret_cast<uint32_t*>(&hi);
                *(uint2*)&Vp[((size_t)b * CCH + m0 + row) * HW + n0 + ch * 4] = o;
            }
        } else {  // MODE 4
            float gamma = __ldg(gammap);
#pragma unroll
            for (int u = 0; u < 16; ++u) {
                int idx = tid + u * 256;
                int row = idx >> 5, ch = idx & 31;
                float4 v = *(float4*)&st[row * EPI_STRIDE + ch * 4];
                size_t off = ((size_t)b * CCH + m0 + row) * HW + n0 + ch * 4;
                float4 uv = *(const float4*)(U + off);
                float4 o;
                o.x = fmaf(gamma, v.x, uv.x); o.y = fmaf(gamma, v.y, uv.y);
                o.z = fmaf(gamma, v.z, uv.z); o.w = fmaf(gamma, v.w, uv.w);
                *(float4*)(Out + off) = o;
            }
        }
    }
}

// ---------------------------------------------------------------------------
// prep kernels
// ---------------------------------------------------------------------------
__global__ void wconv_kernel(const float* __restrict__ qw,
                             const float* __restrict__ vw,
                             const float* __restrict__ kw2) {
    int i = blockIdx.x * 256 + threadIdx.x;
    if (i < 65536)       g_Wq[i]          = __float2bfloat16(qw[i]);
    else if (i < 131072) g_Wv[i - 65536]  = __float2bfloat16(vw[i - 65536]);
    else if (i < 147456) g_Wk[i - 131072] = __float2bfloat16(kw2[i - 131072]);
}

__global__ void transU_kernel(const float* __restrict__ U) {
    __shared__ float t[32][33];
    int b = blockIdx.z, c0 = blockIdx.y * 32, j0 = blockIdx.x * 32;
    int tx = threadIdx.x, ty = threadIdx.y;
    const float* Ub = U + ((size_t)b * CCH + c0) * HW + j0;
#pragma unroll
    for (int k = 0; k < 4; ++k)
        t[ty + 8 * k][tx] = Ub[(size_t)(ty + 8 * k) * HW + tx];
    __syncthreads();
    bf16* Utb = g_Ut + ((size_t)b * HW + j0) * CCH + c0;
#pragma unroll
    for (int k = 0; k < 4; ++k)
        Utb[(size_t)(ty + 8 * k) * CCH + tx] = __float2bfloat16(t[tx][ty + 8 * k]);
}

__global__ void keymid_kernel(const float* __restrict__ bmap,
                              const float* __restrict__ w1,
                              const float* __restrict__ bs,
                              const float* __restrict__ bbias,
                              const float* __restrict__ bmean,
                              const float* __restrict__ bvar) {
    int idx = blockIdx.x * 256 + threadIdx.x;   // BATCH*HW*MID, m fastest
    int m = idx & 63, p = (idx >> 6) & (HW - 1), b = idx >> 18;
    float inv = bs[m] * rsqrtf(bvar[m] + 1e-5f);
    float a   = w1[m] * inv;
    float bb  = bbias[m] - bmean[m] * inv;
    int y = p >> 6, x = p & 63;
    float s = bmap[b * 16384 + y * 256 + x * 2];
    g_Tt[idx] = __float2bfloat16(fmaxf(fmaf(a, s, bb), 0.0f));
}

__global__ void zinv_kernel() {
    int t = blockIdx.x * 256 + threadIdx.x;     // BATCH*HW
    int b = t >> 12, i = t & (HW - 1);
    float s = 0.0f;
#pragma unroll 8
    for (int p = 0; p < 256; ++p)
        s += g_Zp[((size_t)b * 256 + p) * HW + i];
    g_Zi[t] = 1.0f / s;
}

// ---------------------------------------------------------------------------
extern "C" void kernel_launch(void* const* d_in, const int* in_sizes, int n_in,
                              void* d_out, int out_size)
{
    const float* bmap     = (const float*)d_in[0];
    const float* U        = (const float*)d_in[1];
    const float* key_w1   = (const float*)d_in[2];
    const float* bn_scale = (const float*)d_in[3];
    const float* bn_bias  = (const float*)d_in[4];
    const float* bn_mean  = (const float*)d_in[5];
    const float* bn_var   = (const float*)d_in[6];
    const float* key_w2   = (const float*)d_in[7];
    const float* query_w  = (const float*)d_in[8];
    const float* value_w  = (const float*)d_in[9];
    const float* gamma    = (const float*)d_in[10];
    float* out = (float*)d_out;

    cudaFuncSetAttribute(gemm_hmma<0>, cudaFuncAttributeMaxDynamicSharedMemorySize, SMEM_BYTES);
    cudaFuncSetAttribute(gemm_hmma<1>, cudaFuncAttributeMaxDynamicSharedMemorySize, SMEM_BYTES);
    cudaFuncSetAttribute(gemm_hmma<2>, cudaFuncAttributeMaxDynamicSharedMemorySize, SMEM_BYTES);
    cudaFuncSetAttribute(gemm_hmma<3>, cudaFuncAttributeMaxDynamicSharedMemorySize, SMEM_BYTES);
    cudaFuncSetAttribute(gemm_hmma<4>, cudaFuncAttributeMaxDynamicSharedMemorySize, SMEM_BYTES);

    // prep
    wconv_kernel<<<576, 256>>>(query_w, value_w, key_w2);
    transU_kernel<<<dim3(HW / 32, CCH / 32, BATCH), dim3(32, 8)>>>(U);
    keymid_kernel<<<(BATCH * HW * MID) / 256, 256>>>(bmap, key_w1, bn_scale,
                                                     bn_bias, bn_mean, bn_var);
    // Qt[j][c], Kt[p][c]
    gemm_hmma<0><<<dim3(2, 32, BATCH), 256, SMEM_BYTES>>>(U, gamma, out);
    gemm_hmma<1><<<dim3(2, 32, BATCH), 256, SMEM_BYTES>>>(U, gamma, out);
    // S[j][i] = exp(Q_j . K_i) + Z partials
    gemm_hmma<2><<<dim3(32, 32, BATCH), 256, SMEM_BYTES>>>(U, gamma, out);
    // Zinv
    zinv_kernel<<<(BATCH * HW) / 256, 256>>>();
    // Vz[c][i] = (Wv @ U)[c][i] * Zinv[i]
    gemm_hmma<3><<<dim3(32, 2, BATCH), 256, SMEM_BYTES>>>(U, gamma, out);
    // out[c][j] = gamma * sum_i Vz[c][i] S[j][i] + U[c][j]
    gemm_hmma<4><<<dim3(32, 2, BATCH), 256, SMEM_BYTES>>>(U, gamma, out);
}